// round 10
// baseline (speedup 1.0000x reference)
#include <cuda_runtime.h>
#include <cstdint>

#define N_NODES 100000
#define N_EDGES 1600000
#define D_FEAT  50
#define PADF    64                        // floats per padded row (256B)
#define PAD4    16                        // float4 per padded row
#define EDGE2        (N_EDGES / 2)
#define EDGE2_BLOCKS ((EDGE2 + 255) / 256)
#define CONV2        (N_NODES * 32)       // float2 slots per padded buffer
#define CONV_BLOCKS  ((CONV2 + 255) / 256)
#define SCAN_BLOCKS  ((N_NODES + 1023) / 1024)   // 98

static __device__ __constant__ float TAU = 0.1f / 1.8f;   // gamma * lambda

struct NodeInfo { int start; int cnt; float isqo; float isqi; };

// ---------------- scratch (device globals; allocation forbidden) -----------
struct Zeroed {                       // zeroed by ONE cudaMemsetAsync
    float outdeg[N_NODES];
    float indeg [N_NODES];
    int   cnt   [N_NODES];
    unsigned long long tile[SCAN_BLOCKS];   // {flag<<32 | inclusive prefix}
};
__device__ Zeroed   g_z;
__device__ NodeInfo g_nodes [N_NODES];
__device__ int      g_cursor[N_NODES];
__device__ float2   g_edge  [N_EDGES];    // {src (bits), ew*isqo[src]}
__device__ float    g_featp [N_NODES * PADF];   // padded fp32 feat
__device__ float    g_x1    [N_NODES * PADF];
__device__ float    g_x2    [N_NODES * PADF];

// ---------------- pass 1: degrees (2 edges/thread) + feat padding ----------
__global__ void __launch_bounds__(256)
k_deg_feat(const float* __restrict__ ew, const int* __restrict__ src,
           const int* __restrict__ dst, const float* __restrict__ feat) {
    if (blockIdx.x < EDGE2_BLOCKS) {
        int t = blockIdx.x * 256 + threadIdx.x;
        if (t < EDGE2) {
            float2 w2 = reinterpret_cast<const float2*>(ew)[t];
            int2   s2 = reinterpret_cast<const int2*>(src)[t];
            int2   d2 = reinterpret_cast<const int2*>(dst)[t];
            atomicAdd(&g_z.outdeg[s2.x], w2.x);
            atomicAdd(&g_z.outdeg[s2.y], w2.y);
            atomicAdd(&g_z.indeg [d2.x], w2.x);
            atomicAdd(&g_z.indeg [d2.y], w2.y);
            atomicAdd(&g_z.cnt   [d2.x], 1);
            atomicAdd(&g_z.cnt   [d2.y], 1);
        }
    } else {
        int j = (blockIdx.x - EDGE2_BLOCKS) * 256 + threadIdx.x;   // float2 idx
        if (j < CONV2) {
            int row = j >> 5, c2 = j & 31;
            float2 v = make_float2(0.f, 0.f);
            if (c2 < 25)
                v = reinterpret_cast<const float2*>(feat)[row * 25 + c2];
            reinterpret_cast<float2*>(g_featp)[row * 32 + c2] = v;
        }
    }
}

// ---------------- pass 2: chained-lookback scan + node prep ----------------
__global__ void __launch_bounds__(1024)
k_scanall() {
    int b = blockIdx.x, t = threadIdx.x;
    int i = b * 1024 + t;
    int v = (i < N_NODES) ? g_z.cnt[i] : 0;

    int lane = t & 31, w = t >> 5;
    int x = v;
    #pragma unroll
    for (int o = 1; o < 32; o <<= 1) {
        int y = __shfl_up_sync(0xffffffffu, x, o);
        if (lane >= o) x += y;
    }
    __shared__ int wsum[32];
    if (lane == 31) wsum[w] = x;
    __syncthreads();
    if (w == 0) {
        int s = wsum[lane];
        #pragma unroll
        for (int o = 1; o < 32; o <<= 1) {
            int y = __shfl_up_sync(0xffffffffu, s, o);
            if (lane >= o) s += y;
        }
        wsum[lane] = s;
    }
    __syncthreads();
    int incl = x + (w ? wsum[w - 1] : 0);
    int blocktotal = wsum[31];

    __shared__ int s_pref;
    if (t == 0) {
        int pref = 0;
        if (b > 0) {
            unsigned long long u;
            do { u = atomicAdd(&g_z.tile[b - 1], 0ULL); } while (!(u >> 32));
            pref = (int)(u & 0xffffffffULL);
        }
        atomicExch(&g_z.tile[b], (1ULL << 32) | (unsigned)(pref + blocktotal));
        s_pref = pref;
    }
    __syncthreads();

    if (i < N_NODES) {
        int start = s_pref + incl - v;
        NodeInfo ni;
        ni.start = start;
        ni.cnt   = v;
        ni.isqo  = rsqrtf(g_z.outdeg[i] + 1.0f);   // +1 = self-loop weight
        ni.isqi  = rsqrtf(g_z.indeg [i] + 1.0f);
        g_nodes[i]  = ni;
        g_cursor[i] = start;
    }
}

// ---------------- pass 3: scatter edges into CSR-by-dst --------------------
__global__ void __launch_bounds__(256)
k_scatter(const float* __restrict__ ew, const int* __restrict__ src,
          const int* __restrict__ dst) {
    int t = blockIdx.x * 256 + threadIdx.x;
    if (t >= EDGE2) return;
    float2 w2 = reinterpret_cast<const float2*>(ew)[t];
    int2   s2 = reinterpret_cast<const int2*>(src)[t];
    int2   d2 = reinterpret_cast<const int2*>(dst)[t];
    // isqi[dst] is factored out of the row sum (applied in SpMM epilogue)
    float wa = w2.x * g_nodes[s2.x].isqo;
    float wb = w2.y * g_nodes[s2.y].isqo;
    int pa = atomicAdd(&g_cursor[d2.x], 1);
    int pb = atomicAdd(&g_cursor[d2.y], 1);
    g_edge[pa] = make_float2(__int_as_float(s2.x), wa);
    g_edge[pb] = make_float2(__int_as_float(s2.y), wb);
}

// ---------------- fused SpMM + prox: warp/node, 2 edges per warp-instr -----
__device__ __forceinline__ void fma4(float4& a, float s, const float4& r) {
    a.x = fmaf(s, r.x, a.x);
    a.y = fmaf(s, r.y, a.y);
    a.z = fmaf(s, r.z, a.z);
    a.w = fmaf(s, r.w, a.w);
}

template <bool LAST>
__global__ void __launch_bounds__(256)
k_spmm_prox(const float4* __restrict__ xin,    // padded rows: 16 float4 each
            void* __restrict__ xout) {
    int warp = (blockIdx.x * blockDim.x + threadIdx.x) >> 5;
    int lane = threadIdx.x & 31;
    if (warp >= N_NODES) return;
    const int i    = warp;
    const int half = lane >> 4;             // 0: even edge, 1: odd edge
    const int l16  = lane & 15;

    const NodeInfo ni = g_nodes[i];         // single LDG.128

    float4 acc;
    {
        float4 xv = xin[i * PAD4 + l16];    // self-loop (lower half carries it)
        float w0 = half ? 0.f : ni.isqo;
        acc.x = w0 * xv.x; acc.y = w0 * xv.y;
        acc.z = w0 * xv.z; acc.w = w0 * xv.w;
    }

    const float2* __restrict__ ep = g_edge + ni.start;
    const int cnt = ni.cnt;
    int e = 0;
    for (; e + 4 <= cnt; e += 4) {          // 2 row-pairs in flight
        float2 mA = ep[e + half];
        float2 mB = ep[e + 2 + half];
        float4 rA = xin[__float_as_int(mA.x) * PAD4 + l16];
        float4 rB = xin[__float_as_int(mB.x) * PAD4 + l16];
        fma4(acc, mA.y, rA);
        fma4(acc, mB.y, rB);
    }
    if (e + 2 <= cnt) {
        float2 m = ep[e + half];
        float4 r = xin[__float_as_int(m.x) * PAD4 + l16];
        fma4(acc, m.y, r);
        e += 2;
    }
    if (e < cnt) {                          // odd tail: broadcast, hi half x0
        float2 m = ep[e];
        float4 r = xin[__float_as_int(m.x) * PAD4 + l16];
        float wt = half ? 0.f : m.y;
        fma4(acc, wt, r);
    }

    // combine halves, then apply the factored isqi[dst]
    acc.x += __shfl_xor_sync(0xffffffffu, acc.x, 16);
    acc.y += __shfl_xor_sync(0xffffffffu, acc.y, 16);
    acc.z += __shfl_xor_sync(0xffffffffu, acc.z, 16);
    acc.w += __shfl_xor_sync(0xffffffffu, acc.w, 16);
    acc.x *= ni.isqi; acc.y *= ni.isqi;
    acc.z *= ni.isqi; acc.w *= ni.isqi;

    // proximal L2,1 on (agg - feat); y == agg since gamma*2*(1-lam) == 1
    float4 f = reinterpret_cast<const float4*>(g_featp)[i * PAD4 + l16];
    float dx0 = acc.x - f.x, dx1 = acc.y - f.y;
    float dx2 = acc.z - f.z, dx3 = acc.w - f.w;
    float sq = dx0 * dx0 + dx1 * dx1 + dx2 * dx2 + dx3 * dx3;
    #pragma unroll
    for (int o = 8; o; o >>= 1)             // halves identical: reduce 16 lanes
        sq += __shfl_xor_sync(0xffffffffu, sq, o);
    float nrm = sqrtf(sq);
    float scale = (nrm > 0.f) ? fmaxf(nrm - TAU, 0.f) / nrm : 0.f;

    float o0 = f.x + scale * dx0, o1 = f.y + scale * dx1;
    float o2 = f.z + scale * dx2, o3 = f.w + scale * dx3;

    if (half == 0) {
        if (LAST) {                          // dense 50-float rows, 8B aligned
            float2* op = reinterpret_cast<float2*>((float*)xout + i * D_FEAT);
            int c = 4 * l16;
            if (c     < D_FEAT) op[2 * l16]     = make_float2(o0, o1);
            if (c + 2 < D_FEAT) op[2 * l16 + 1] = make_float2(o2, o3);
        } else {                             // padded scratch, pad stays zero
            reinterpret_cast<float4*>(xout)[i * PAD4 + l16] =
                make_float4(o0, o1, o2, o3);
        }
    }
}

// ---------------- launch ----------------------------------------------------
extern "C" void kernel_launch(void* const* d_in, const int* in_sizes, int n_in,
                              void* d_out, int out_size) {
    const float* feat = (const float*)d_in[0];
    const float* ew   = (const float*)d_in[1];
    const int*   src  = (const int*)d_in[2];
    const int*   dst  = (const int*)d_in[3];

    void *zptr, *fp, *x1, *x2;
    cudaGetSymbolAddress(&zptr, g_z);
    cudaGetSymbolAddress(&fp,   g_featp);
    cudaGetSymbolAddress(&x1,   g_x1);
    cudaGetSymbolAddress(&x2,   g_x2);

    cudaMemsetAsync(zptr, 0, sizeof(Zeroed));
    k_deg_feat<<<EDGE2_BLOCKS + CONV_BLOCKS, 256>>>(ew, src, dst, feat);
    k_scanall <<<SCAN_BLOCKS, 1024>>>();
    k_scatter <<<EDGE2_BLOCKS, 256>>>(ew, src, dst);

    const int spmmBlocks = (N_NODES * 32 + 255) / 256;   // warp per node
    k_spmm_prox<false><<<spmmBlocks, 256>>>((const float4*)fp, x1);
    k_spmm_prox<false><<<spmmBlocks, 256>>>((const float4*)x1, x2);
    k_spmm_prox<true ><<<spmmBlocks, 256>>>((const float4*)x2, d_out);
}